// round 2
// baseline (speedup 1.0000x reference)
#include <cuda_runtime.h>
#include <cstdint>

#define NN 150000
#define NE 2400000

// Scratch (static __device__ — no allocations allowed)
__device__ float g_hw[NN * 32];      // h@W2 rows (19.2 MB)
__device__ float g_aggx[NN * 6];     // aggregated x (3.6 MB)
__device__ float g_dinv[NN];
__device__ int   g_off[NN + 1];      // CSR row offsets (by dst)
__device__ int   g_cursor[NN];       // hist, then fill cursor
__device__ int   g_csr[NE];          // src indices grouped by dst
__device__ int   g_partial[256];     // scan partials

// ---------------------------------------------------------------------------
__global__ void k_zero(int n) {
    int i = blockIdx.x * blockDim.x + threadIdx.x;
    if (i < n) g_cursor[i] = 0;
}

__global__ void k_hist(const int* __restrict__ dst, int ne) {
    int e = blockIdx.x * blockDim.x + threadIdx.x;
    if (e < ne) atomicAdd(&g_cursor[dst[e]], 1);
}

// block-local exclusive scan of g_cursor -> g_off, partial sums -> g_partial
__global__ void k_scan1(int n) {
    __shared__ int sh[1024];
    int i = blockIdx.x * 1024 + threadIdx.x;
    int v = (i < n) ? g_cursor[i] : 0;
    sh[threadIdx.x] = v;
    __syncthreads();
#pragma unroll
    for (int o = 1; o < 1024; o <<= 1) {
        int t = 0;
        if ((int)threadIdx.x >= o) t = sh[threadIdx.x - o];
        __syncthreads();
        if ((int)threadIdx.x >= o) sh[threadIdx.x] += t;
        __syncthreads();
    }
    if (i < n) g_off[i] = sh[threadIdx.x] - v;
    if (threadIdx.x == 1023) g_partial[blockIdx.x] = sh[1023];
}

// exclusive scan of partials (single block, nb <= 256)
__global__ void k_scan2(int nb) {
    __shared__ int sh[256];
    int v = ((int)threadIdx.x < nb) ? g_partial[threadIdx.x] : 0;
    sh[threadIdx.x] = v;
    __syncthreads();
#pragma unroll
    for (int o = 1; o < 256; o <<= 1) {
        int t = 0;
        if ((int)threadIdx.x >= o) t = sh[threadIdx.x - o];
        __syncthreads();
        if ((int)threadIdx.x >= o) sh[threadIdx.x] += t;
        __syncthreads();
    }
    if ((int)threadIdx.x < nb) g_partial[threadIdx.x] = sh[threadIdx.x] - v;
}

__global__ void k_scan3(int n, int ne) {
    int i = blockIdx.x * blockDim.x + threadIdx.x;
    if (i < n) g_off[i] += g_partial[i >> 10];
    if (i == 0) g_off[n] = ne;
}

// cursor = offsets copy; dinv = rsqrt(deg+1)
__global__ void k_prep(int n) {
    int i = blockIdx.x * blockDim.x + threadIdx.x;
    if (i >= n) return;
    int b = g_off[i], e = g_off[i + 1];
    g_cursor[i] = b;
    g_dinv[i] = rsqrtf((float)(e - b) + 1.0f);
}

__global__ void k_fill(const int* __restrict__ src, const int* __restrict__ dst, int ne) {
    int e = blockIdx.x * blockDim.x + threadIdx.x;
    if (e >= ne) return;
    int d = dst[e];
    int pos = atomicAdd(&g_cursor[d], 1);
    g_csr[pos] = src[e];
}

// ---------------------------------------------------------------------------
// aggx[d] = x[d]*dinv_d^2 + sum_s x[s]*dinv[s]*dinv[d]   (6 dims, via float2 x3)
__global__ void k_aggx(const float* __restrict__ x, int n) {
    int i = blockIdx.x * blockDim.x + threadIdx.x;
    if (i >= n) return;
    const float2* x2 = (const float2*)x;
    float dd = g_dinv[i];
    float d2 = dd * dd;
    float2 a0 = x2[i * 3 + 0], a1 = x2[i * 3 + 1], a2 = x2[i * 3 + 2];
    float c0 = a0.x * d2, c1 = a0.y * d2, c2 = a1.x * d2;
    float c3 = a1.y * d2, c4 = a2.x * d2, c5 = a2.y * d2;
    int b = g_off[i], e = g_off[i + 1];
    int j = b;
    for (; j + 1 < e; j += 2) {
        int s0 = g_csr[j], s1 = g_csr[j + 1];
        float n0 = g_dinv[s0] * dd, n1 = g_dinv[s1] * dd;
        float2 p0 = x2[s0 * 3 + 0], p1 = x2[s0 * 3 + 1], p2 = x2[s0 * 3 + 2];
        float2 q0 = x2[s1 * 3 + 0], q1 = x2[s1 * 3 + 1], q2 = x2[s1 * 3 + 2];
        c0 += p0.x * n0; c1 += p0.y * n0; c2 += p1.x * n0;
        c3 += p1.y * n0; c4 += p2.x * n0; c5 += p2.y * n0;
        c0 += q0.x * n1; c1 += q0.y * n1; c2 += q1.x * n1;
        c3 += q1.y * n1; c4 += q2.x * n1; c5 += q2.y * n1;
    }
    if (j < e) {
        int s0 = g_csr[j];
        float n0 = g_dinv[s0] * dd;
        float2 p0 = x2[s0 * 3 + 0], p1 = x2[s0 * 3 + 1], p2 = x2[s0 * 3 + 2];
        c0 += p0.x * n0; c1 += p0.y * n0; c2 += p1.x * n0;
        c3 += p1.y * n0; c4 += p2.x * n0; c5 += p2.y * n0;
    }
    float2* o2 = (float2*)g_aggx;
    o2[i * 3 + 0] = make_float2(c0, c1);
    o2[i * 3 + 1] = make_float2(c2, c3);
    o2[i * 3 + 2] = make_float2(c4, c5);
}

// ---------------------------------------------------------------------------
// node GEMMs: h = relu(aggx@W1 + b1); hw = h@W2 -> g_hw
__global__ void k_node(const float* __restrict__ W1, const float* __restrict__ b1,
                       const float* __restrict__ W2, int n) {
    __shared__ float sW1[6 * 32];
    __shared__ float sb1[32];
    __shared__ float sW2[32 * 32];
    for (int t = threadIdx.x; t < 192; t += blockDim.x) sW1[t] = W1[t];
    for (int t = threadIdx.x; t < 1024; t += blockDim.x) sW2[t] = W2[t];
    if (threadIdx.x < 32) sb1[threadIdx.x] = b1[threadIdx.x];
    __syncthreads();
    int i = blockIdx.x * blockDim.x + threadIdx.x;
    if (i >= n) return;

    float a[6];
#pragma unroll
    for (int k = 0; k < 6; k++) a[k] = g_aggx[i * 6 + k];

    float h[32];
#pragma unroll
    for (int j = 0; j < 32; j++) {
        float s = sb1[j];
#pragma unroll
        for (int k = 0; k < 6; k++) s += a[k] * sW1[k * 32 + j];
        h[j] = fmaxf(s, 0.f);
    }
    float acc[32];
#pragma unroll
    for (int j = 0; j < 32; j++) acc[j] = 0.f;
#pragma unroll
    for (int k = 0; k < 32; k++) {
        float hk = h[k];
#pragma unroll
        for (int j = 0; j < 32; j++) acc[j] += hk * sW2[k * 32 + j];
    }
    float4* o = (float4*)&g_hw[i * 32];
#pragma unroll
    for (int q = 0; q < 8; q++)
        o[q] = make_float4(acc[4*q], acc[4*q+1], acc[4*q+2], acc[4*q+3]);
}

// ---------------------------------------------------------------------------
// warp-per-node: features = gather(hw) + b2; write features; fused MLP heads
__global__ void k_feat(const float* __restrict__ b2,
                       const float* __restrict__ Wt1, const float* __restrict__ bt1,
                       const float* __restrict__ Wt2, const float* __restrict__ bt2,
                       const float* __restrict__ Wa1, const float* __restrict__ ba1,
                       const float* __restrict__ Wa2, const float* __restrict__ ba2,
                       float* __restrict__ out, int n) {
    __shared__ float s_Wt1[32 * 16];
    __shared__ float s_Wa1[32 * 16];
    __shared__ float s_Wa2[16 * 6];
    __shared__ float s_b2[32];
    __shared__ float s_bt1[16], s_Wt2[16], s_ba1[16], s_ba2[6];
    __shared__ float s_bt2;
    __shared__ float fsh[8][32];   // 8 warps/block

    for (int t = threadIdx.x; t < 512; t += blockDim.x) { s_Wt1[t] = Wt1[t]; s_Wa1[t] = Wa1[t]; }
    for (int t = threadIdx.x; t < 96; t += blockDim.x) s_Wa2[t] = Wa2[t];
    if (threadIdx.x < 32) s_b2[threadIdx.x] = b2[threadIdx.x];
    if (threadIdx.x < 16) { s_bt1[threadIdx.x] = bt1[threadIdx.x];
                            s_Wt2[threadIdx.x] = Wt2[threadIdx.x];
                            s_ba1[threadIdx.x] = ba1[threadIdx.x]; }
    if (threadIdx.x < 6)  s_ba2[threadIdx.x] = ba2[threadIdx.x];
    if (threadIdx.x == 0) s_bt2 = bt2[0];
    __syncthreads();

    int w = threadIdx.x >> 5;                       // warp in block
    int lane = threadIdx.x & 31;
    int d = blockIdx.x * 8 + w;                     // node
    if (d >= n) return;

    float dd = g_dinv[d];
    float acc = g_hw[(long)d * 32 + lane] * (dd * dd);
    int b = g_off[d], e = g_off[d + 1];
    int j = b;
    for (; j + 1 < e; j += 2) {
        int s0 = g_csr[j], s1 = g_csr[j + 1];
        float n0 = g_dinv[s0] * dd, n1 = g_dinv[s1] * dd;
        float v0 = g_hw[(long)s0 * 32 + lane];
        float v1 = g_hw[(long)s1 * 32 + lane];
        acc += v0 * n0;
        acc += v1 * n1;
    }
    if (j < e) {
        int s0 = g_csr[j];
        acc += g_hw[(long)s0 * 32 + lane] * (g_dinv[s0] * dd);
    }
    float f = acc + s_b2[lane];

    // features output at offset 7*n
    out[(long)7 * n + (long)d * 32 + lane] = f;

    fsh[w][lane] = f;
    __syncwarp();

    // hidden layers: lanes 0-15 -> topo hidden, lanes 16-31 -> attr hidden
    float hid;
    if (lane < 16) {
        float s = s_bt1[lane];
#pragma unroll
        for (int k = 0; k < 32; k++) s += fsh[w][k] * s_Wt1[k * 16 + lane];
        hid = fmaxf(s, 0.f);
    } else {
        int jj = lane - 16;
        float s = s_ba1[jj];
#pragma unroll
        for (int k = 0; k < 32; k++) s += fsh[w][k] * s_Wa1[k * 16 + jj];
        hid = fmaxf(s, 0.f);
    }
    __syncwarp();
    fsh[w][lane] = hid;
    __syncwarp();

    if (lane == 0) {
        float topo = s_bt2;
#pragma unroll
        for (int k = 0; k < 16; k++) topo += fsh[w][k] * s_Wt2[k];
        out[d] = topo;
    } else if (lane >= 1 && lane <= 6) {
        int m = lane - 1;
        float s = s_ba2[m];
#pragma unroll
        for (int k = 0; k < 16; k++) s += fsh[w][16 + k] * s_Wa2[k * 6 + m];
        long nb = n;
        if (m < 3) out[nb + (long)d * 3 + m] = s;
        else       out[nb * 4 + (long)d * 3 + (m - 3)] = s;
    }
}

// ---------------------------------------------------------------------------
extern "C" void kernel_launch(void* const* d_in, const int* in_sizes, int n_in,
                              void* d_out, int out_size) {
    const float* x   = (const float*)d_in[0];
    const int*   ei  = (const int*)d_in[1];
    const float* W1  = (const float*)d_in[2];
    const float* b1  = (const float*)d_in[3];
    const float* W2  = (const float*)d_in[4];
    const float* b2  = (const float*)d_in[5];
    const float* Wt1 = (const float*)d_in[6];
    const float* bt1 = (const float*)d_in[7];
    const float* Wt2 = (const float*)d_in[8];
    const float* bt2 = (const float*)d_in[9];
    const float* Wa1 = (const float*)d_in[10];
    const float* ba1 = (const float*)d_in[11];
    const float* Wa2 = (const float*)d_in[12];
    const float* ba2 = (const float*)d_in[13];
    float* out = (float*)d_out;

    int n  = in_sizes[0] / 6;
    int ne = in_sizes[1] / 2;
    const int* src = ei;
    const int* dst = ei + ne;

    const int B = 256;
    int gn = (n + B - 1) / B;
    int ge = (ne + B - 1) / B;
    int nb_scan = (n + 1023) / 1024;
    int gfeat = (n + 7) / 8;

    k_zero <<<gn, B>>>(n);
    k_hist <<<ge, B>>>(dst, ne);
    k_scan1<<<nb_scan, 1024>>>(n);
    k_scan2<<<1, 256>>>(nb_scan);
    k_scan3<<<gn, B>>>(n, ne);
    k_prep <<<gn, B>>>(n);
    k_fill <<<ge, B>>>(src, dst, ne);
    k_aggx <<<gn, B>>>(x, n);
    k_node <<<gn, B>>>(W1, b1, W2, n);
    k_feat <<<gfeat, B>>>(b2, Wt1, bt1, Wt2, bt2, Wa1, ba1, Wa2, ba2, out, n);
}

// round 3
// speedup vs baseline: 1.5272x; 1.5272x over previous
#include <cuda_runtime.h>
#include <cstdint>

#define NN 150000
#define NE 2400000

// Scratch (static __device__ — no allocations allowed)
__device__ float g_xs[NN * 8];      // x * dinv, padded 6->8 (4.8 MB)
__device__ float g_agg1[NN * 8];    // pass-1 accumulator     (4.8 MB)
__device__ float g_hs[NN * 32];     // (h@W2) * dinv          (19.2 MB)
__device__ float g_agg2[NN * 32];   // pass-2 accumulator     (19.2 MB)
__device__ float g_dinv[NN];        // deg -> dinv

// ---------------------------------------------------------------------------
// 1) degree init: deg = 1 (self loop)
__global__ void k_deg_init(int n) {
    int i = blockIdx.x * blockDim.x + threadIdx.x;
    if (i < n) g_dinv[i] = 1.0f;
}

// 2) degree accumulate over dst
__global__ void k_deg_edges(const int* __restrict__ dst, int ne) {
    int e = blockIdx.x * blockDim.x + threadIdx.x;
    if (e < ne) {
        float* p = &g_dinv[__ldg(&dst[e])];
        asm volatile("red.global.add.f32 [%0], %1;" :: "l"(p), "f"(1.0f) : "memory");
    }
}

// 3) prep: dinv = rsqrt(deg); xs = x*dinv (pad 8); agg1 = xs (self-loop init)
__global__ void k_prep(const float* __restrict__ x, int n) {
    int i = blockIdx.x * blockDim.x + threadIdx.x;
    if (i >= n) return;
    float dinv = rsqrtf(g_dinv[i]);
    g_dinv[i] = dinv;
    const float2* x2 = (const float2*)x;   // x rows are 24B, 8B-aligned
    float2 a0 = __ldg(&x2[i * 3 + 0]);
    float2 a1 = __ldg(&x2[i * 3 + 1]);
    float2 a2 = __ldg(&x2[i * 3 + 2]);
    float4 v0 = make_float4(a0.x * dinv, a0.y * dinv, a1.x * dinv, a1.y * dinv);
    float4 v1 = make_float4(a2.x * dinv, a2.y * dinv, 0.f, 0.f);
    float4* xs4 = (float4*)g_xs;
    float4* ag4 = (float4*)g_agg1;
    xs4[i * 2 + 0] = v0; xs4[i * 2 + 1] = v1;
    ag4[i * 2 + 0] = v0; ag4[i * 2 + 1] = v1;
}

// 4) pass-1 edge scatter: agg1[dst] += xs[src]  (thread per edge, 2x v4 RED)
__global__ void k_scat1(const int* __restrict__ src, const int* __restrict__ dst, int ne) {
    int e = blockIdx.x * blockDim.x + threadIdx.x;
    if (e >= ne) return;
    int s = __ldg(&src[e]);
    int d = __ldg(&dst[e]);
    const float4* xs4 = (const float4*)g_xs;
    float4 v0 = __ldg(&xs4[(long)s * 2 + 0]);
    float4 v1 = __ldg(&xs4[(long)s * 2 + 1]);
    float4* p = (float4*)&g_agg1[(long)d * 8];
    asm volatile("red.global.add.v4.f32 [%0], {%1, %2, %3, %4};"
                 :: "l"(p), "f"(v0.x), "f"(v0.y), "f"(v0.z), "f"(v0.w) : "memory");
    asm volatile("red.global.add.v2.f32 [%0], {%1, %2};"
                 :: "l"(p + 1), "f"(v1.x), "f"(v1.y) : "memory");
}

// 5) node: aggx = dinv*agg1; h = relu(aggx@W1+b1); hw = h@W2;
//    hs = hw*dinv -> g_hs; agg2 init = hs (self-loop)
__global__ void k_node(const float* __restrict__ W1, const float* __restrict__ b1,
                       const float* __restrict__ W2, int n) {
    __shared__ float sW1[6 * 32];
    __shared__ float sb1[32];
    __shared__ float sW2[32 * 32];
    for (int t = threadIdx.x; t < 192; t += blockDim.x) sW1[t] = W1[t];
    for (int t = threadIdx.x; t < 1024; t += blockDim.x) sW2[t] = W2[t];
    if (threadIdx.x < 32) sb1[threadIdx.x] = b1[threadIdx.x];
    __syncthreads();
    int i = blockIdx.x * blockDim.x + threadIdx.x;
    if (i >= n) return;

    float dinv = g_dinv[i];
    float a[6];
#pragma unroll
    for (int k = 0; k < 6; k++) a[k] = g_agg1[i * 8 + k] * dinv;

    float h[32];
#pragma unroll
    for (int j = 0; j < 32; j++) {
        float s = sb1[j];
#pragma unroll
        for (int k = 0; k < 6; k++) s += a[k] * sW1[k * 32 + j];
        h[j] = fmaxf(s, 0.f);
    }
    float acc[32];
#pragma unroll
    for (int j = 0; j < 32; j++) acc[j] = 0.f;
#pragma unroll
    for (int k = 0; k < 32; k++) {
        float hk = h[k];
#pragma unroll
        for (int j = 0; j < 32; j++) acc[j] += hk * sW2[k * 32 + j];
    }
    float4* hs4 = (float4*)&g_hs[(long)i * 32];
    float4* ag4 = (float4*)&g_agg2[(long)i * 32];
#pragma unroll
    for (int q = 0; q < 8; q++) {
        float4 v = make_float4(acc[4*q] * dinv, acc[4*q+1] * dinv,
                               acc[4*q+2] * dinv, acc[4*q+3] * dinv);
        hs4[q] = v;
        ag4[q] = v;
    }
}

// 6) pass-2 edge scatter: agg2[dst] += hs[src]  (8 threads/edge, v4 RED each)
__global__ void k_scat2(const int* __restrict__ src, const int* __restrict__ dst, long ne) {
    long tid = (long)blockIdx.x * blockDim.x + threadIdx.x;
    long e = tid >> 3;
    int  c = (int)(tid & 7);
    if (e >= ne) return;
    int s = __ldg(&src[e]);
    int d = __ldg(&dst[e]);
    const float4* hs4 = (const float4*)g_hs;
    float4 v = __ldg(&hs4[(long)s * 8 + c]);
    float4* p = (float4*)&g_agg2[(long)d * 32] + c;
    asm volatile("red.global.add.v4.f32 [%0], {%1, %2, %3, %4};"
                 :: "l"(p), "f"(v.x), "f"(v.y), "f"(v.z), "f"(v.w) : "memory");
}

// 7) heads: features = dinv*agg2 + b2 -> out; two tiny MLPs
__global__ void k_heads(const float* __restrict__ b2,
                        const float* __restrict__ Wt1, const float* __restrict__ bt1,
                        const float* __restrict__ Wt2, const float* __restrict__ bt2,
                        const float* __restrict__ Wa1, const float* __restrict__ ba1,
                        const float* __restrict__ Wa2, const float* __restrict__ ba2,
                        float* __restrict__ out, int n) {
    __shared__ float s_b2[32];
    __shared__ float s_Wt1[32 * 16];
    __shared__ float s_bt1[16];
    __shared__ float s_Wt2[16];
    __shared__ float s_Wa1[32 * 16];
    __shared__ float s_ba1[16];
    __shared__ float s_Wa2[16 * 6];
    __shared__ float s_ba2[6];
    __shared__ float s_bt2;
    for (int t = threadIdx.x; t < 512; t += blockDim.x) { s_Wt1[t] = Wt1[t]; s_Wa1[t] = Wa1[t]; }
    for (int t = threadIdx.x; t < 96;  t += blockDim.x) s_Wa2[t] = Wa2[t];
    if (threadIdx.x < 32) s_b2[threadIdx.x] = b2[threadIdx.x];
    if (threadIdx.x < 16) { s_bt1[threadIdx.x] = bt1[threadIdx.x];
                            s_Wt2[threadIdx.x] = Wt2[threadIdx.x];
                            s_ba1[threadIdx.x] = ba1[threadIdx.x]; }
    if (threadIdx.x < 6)  s_ba2[threadIdx.x] = ba2[threadIdx.x];
    if (threadIdx.x == 0) s_bt2 = bt2[0];
    __syncthreads();

    int i = blockIdx.x * blockDim.x + threadIdx.x;
    if (i >= n) return;

    float dinv = g_dinv[i];
    float f[32];
    const float4* ag4 = (const float4*)&g_agg2[(long)i * 32];
#pragma unroll
    for (int q = 0; q < 8; q++) {
        float4 v = ag4[q];
        f[4*q+0] = v.x * dinv + s_b2[4*q+0];
        f[4*q+1] = v.y * dinv + s_b2[4*q+1];
        f[4*q+2] = v.z * dinv + s_b2[4*q+2];
        f[4*q+3] = v.w * dinv + s_b2[4*q+3];
    }

    float4* fout = (float4*)(out + (long)7 * n + (long)i * 32);
#pragma unroll
    for (int q = 0; q < 8; q++)
        fout[q] = make_float4(f[4*q], f[4*q+1], f[4*q+2], f[4*q+3]);

    float t1[16];
#pragma unroll
    for (int j = 0; j < 16; j++) {
        float s = s_bt1[j];
#pragma unroll
        for (int k = 0; k < 32; k++) s += f[k] * s_Wt1[k * 16 + j];
        t1[j] = fmaxf(s, 0.f);
    }
    float topo = s_bt2;
#pragma unroll
    for (int j = 0; j < 16; j++) topo += t1[j] * s_Wt2[j];
    out[i] = topo;

    float a1[16];
#pragma unroll
    for (int j = 0; j < 16; j++) {
        float s = s_ba1[j];
#pragma unroll
        for (int k = 0; k < 32; k++) s += f[k] * s_Wa1[k * 16 + j];
        a1[j] = fmaxf(s, 0.f);
    }
    float attr[6];
#pragma unroll
    for (int m = 0; m < 6; m++) {
        float s = s_ba2[m];
#pragma unroll
        for (int j = 0; j < 16; j++) s += a1[j] * s_Wa2[j * 6 + m];
        attr[m] = s;
    }
    long nb = n;
    out[nb     + (long)i * 3 + 0] = attr[0];
    out[nb     + (long)i * 3 + 1] = attr[1];
    out[nb     + (long)i * 3 + 2] = attr[2];
    out[nb * 4 + (long)i * 3 + 0] = attr[3];
    out[nb * 4 + (long)i * 3 + 1] = attr[4];
    out[nb * 4 + (long)i * 3 + 2] = attr[5];
}

// ---------------------------------------------------------------------------
extern "C" void kernel_launch(void* const* d_in, const int* in_sizes, int n_in,
                              void* d_out, int out_size) {
    const float* x   = (const float*)d_in[0];
    const int*   ei  = (const int*)d_in[1];
    const float* W1  = (const float*)d_in[2];
    const float* b1  = (const float*)d_in[3];
    const float* W2  = (const float*)d_in[4];
    const float* b2  = (const float*)d_in[5];
    const float* Wt1 = (const float*)d_in[6];
    const float* bt1 = (const float*)d_in[7];
    const float* Wt2 = (const float*)d_in[8];
    const float* bt2 = (const float*)d_in[9];
    const float* Wa1 = (const float*)d_in[10];
    const float* ba1 = (const float*)d_in[11];
    const float* Wa2 = (const float*)d_in[12];
    const float* ba2 = (const float*)d_in[13];
    float* out = (float*)d_out;

    int n  = in_sizes[0] / 6;
    int ne = in_sizes[1] / 2;
    const int* src = ei;
    const int* dst = ei + ne;

    const int B = 256;
    int gn = (n + B - 1) / B;
    int ge = (ne + B - 1) / B;
    long s2 = (long)ne * 8;
    int gs2 = (int)((s2 + B - 1) / B);

    k_deg_init <<<gn, B>>>(n);
    k_deg_edges<<<ge, B>>>(dst, ne);
    k_prep     <<<gn, B>>>(x, n);
    k_scat1    <<<ge, B>>>(src, dst, ne);
    k_node     <<<gn, B>>>(W1, b1, W2, n);
    k_scat2    <<<gs2, B>>>(src, dst, ne);
    k_heads    <<<gn, B>>>(b2, Wt1, bt1, Wt2, bt2, Wa1, ba1, Wa2, ba2, out, n);
}

// round 4
// speedup vs baseline: 1.5873x; 1.0394x over previous
#include <cuda_runtime.h>
#include <cstdint>

#define NN 150000
#define NE 2400000

// Scratch (static __device__ — no allocations allowed)
__device__ float g_xs[NN * 8];      // x * dinv, padded 6->8 (4.8 MB)
__device__ float g_agg1[NN * 8];    // pass-1 accumulator     (4.8 MB)
__device__ float g_hs[NN * 32];     // (h@W2) * dinv          (19.2 MB)
__device__ float g_agg2[NN * 32];   // pass-2 accumulator     (19.2 MB)
__device__ float g_dinv[NN];        // deg -> dinv

// ---------------------------------------------------------------------------
__global__ void k_deg_init(int n) {
    int i = blockIdx.x * blockDim.x + threadIdx.x;
    if (i < n) g_dinv[i] = 1.0f;
}

__global__ void k_deg_edges(const int* __restrict__ dst, int ne) {
    int e = blockIdx.x * blockDim.x + threadIdx.x;
    if (e < ne) {
        float* p = &g_dinv[__ldg(&dst[e])];
        asm volatile("red.global.add.f32 [%0], %1;" :: "l"(p), "f"(1.0f) : "memory");
    }
}

// prep: dinv = rsqrt(deg); xs = x*dinv (pad 8); agg1 = xs (self-loop init)
__global__ void k_prep(const float* __restrict__ x, int n) {
    int i = blockIdx.x * blockDim.x + threadIdx.x;
    if (i >= n) return;
    float dinv = rsqrtf(g_dinv[i]);
    g_dinv[i] = dinv;
    const float2* x2 = (const float2*)x;
    float2 a0 = __ldg(&x2[i * 3 + 0]);
    float2 a1 = __ldg(&x2[i * 3 + 1]);
    float2 a2 = __ldg(&x2[i * 3 + 2]);
    float4 v0 = make_float4(a0.x * dinv, a0.y * dinv, a1.x * dinv, a1.y * dinv);
    float4 v1 = make_float4(a2.x * dinv, a2.y * dinv, 0.f, 0.f);
    float4* xs4 = (float4*)g_xs;
    float4* ag4 = (float4*)g_agg1;
    xs4[i * 2 + 0] = v0; xs4[i * 2 + 1] = v1;
    ag4[i * 2 + 0] = v0; ag4[i * 2 + 1] = v1;
}

// pass-1 edge scatter: agg1[dst] += xs[src], TWO edges per thread for MLP
__global__ void k_scat1(const int* __restrict__ src, const int* __restrict__ dst, int ne) {
    int t = blockIdx.x * blockDim.x + threadIdx.x;
    int half = (ne + 1) >> 1;
    if (t >= half) return;
    int e0 = t, e1 = t + half;
    bool has1 = (e1 < ne);

    int s0 = __ldg(&src[e0]);
    int d0 = __ldg(&dst[e0]);
    int s1 = has1 ? __ldg(&src[e1]) : 0;
    int d1 = has1 ? __ldg(&dst[e1]) : 0;

    const float4* xs4 = (const float4*)g_xs;
    float4 a0 = __ldg(&xs4[(long)s0 * 2 + 0]);
    float4 a1 = __ldg(&xs4[(long)s0 * 2 + 1]);
    float4 b0, b1;
    if (has1) {
        b0 = __ldg(&xs4[(long)s1 * 2 + 0]);
        b1 = __ldg(&xs4[(long)s1 * 2 + 1]);
    }

    float4* p0 = (float4*)&g_agg1[(long)d0 * 8];
    asm volatile("red.global.add.v4.f32 [%0], {%1, %2, %3, %4};"
                 :: "l"(p0), "f"(a0.x), "f"(a0.y), "f"(a0.z), "f"(a0.w) : "memory");
    asm volatile("red.global.add.v2.f32 [%0], {%1, %2};"
                 :: "l"(p0 + 1), "f"(a1.x), "f"(a1.y) : "memory");
    if (has1) {
        float4* p1 = (float4*)&g_agg1[(long)d1 * 8];
        asm volatile("red.global.add.v4.f32 [%0], {%1, %2, %3, %4};"
                     :: "l"(p1), "f"(b0.x), "f"(b0.y), "f"(b0.z), "f"(b0.w) : "memory");
        asm volatile("red.global.add.v2.f32 [%0], {%1, %2};"
                     :: "l"(p1 + 1), "f"(b1.x), "f"(b1.y) : "memory");
    }
}

// node: aggx = dinv*agg1; h = relu(aggx@W1+b1); hw = h@W2; hs = hw*dinv; agg2 = hs
__global__ void k_node(const float* __restrict__ W1, const float* __restrict__ b1,
                       const float* __restrict__ W2, int n) {
    __shared__ float sW1[6 * 32];
    __shared__ float sb1[32];
    __shared__ float sW2[32 * 32];
    for (int t = threadIdx.x; t < 192; t += blockDim.x) sW1[t] = W1[t];
    for (int t = threadIdx.x; t < 1024; t += blockDim.x) sW2[t] = W2[t];
    if (threadIdx.x < 32) sb1[threadIdx.x] = b1[threadIdx.x];
    __syncthreads();
    int i = blockIdx.x * blockDim.x + threadIdx.x;
    if (i >= n) return;

    float dinv = g_dinv[i];
    float a[6];
#pragma unroll
    for (int k = 0; k < 6; k++) a[k] = g_agg1[i * 8 + k] * dinv;

    float h[32];
#pragma unroll
    for (int j = 0; j < 32; j++) {
        float s = sb1[j];
#pragma unroll
        for (int k = 0; k < 6; k++) s += a[k] * sW1[k * 32 + j];
        h[j] = fmaxf(s, 0.f);
    }
    float acc[32];
#pragma unroll
    for (int j = 0; j < 32; j++) acc[j] = 0.f;
#pragma unroll
    for (int k = 0; k < 32; k++) {
        float hk = h[k];
#pragma unroll
        for (int j = 0; j < 32; j++) acc[j] += hk * sW2[k * 32 + j];
    }
    float4* hs4 = (float4*)&g_hs[(long)i * 32];
    float4* ag4 = (float4*)&g_agg2[(long)i * 32];
#pragma unroll
    for (int q = 0; q < 8; q++) {
        float4 v = make_float4(acc[4*q] * dinv, acc[4*q+1] * dinv,
                               acc[4*q+2] * dinv, acc[4*q+3] * dinv);
        hs4[q] = v;
        ag4[q] = v;
    }
}

// pass-2 edge scatter: agg2[dst] += hs[src]; 8 threads/edge-slot, 2 edges/thread
__global__ void k_scat2(const int* __restrict__ src, const int* __restrict__ dst,
                        int ne, int half) {
    long tid = (long)blockIdx.x * blockDim.x + threadIdx.x;
    long e0 = tid >> 3;
    int  c = (int)(tid & 7);
    if (e0 >= half) return;
    long e1 = e0 + half;
    bool has1 = (e1 < ne);

    int s0 = __ldg(&src[e0]);
    int d0 = __ldg(&dst[e0]);
    int s1 = has1 ? __ldg(&src[e1]) : 0;
    int d1 = has1 ? __ldg(&dst[e1]) : 0;

    const float4* hs4 = (const float4*)g_hs;
    float4 v0 = __ldg(&hs4[(long)s0 * 8 + c]);
    float4 v1;
    if (has1) v1 = __ldg(&hs4[(long)s1 * 8 + c]);

    float4* p0 = (float4*)&g_agg2[(long)d0 * 32] + c;
    asm volatile("red.global.add.v4.f32 [%0], {%1, %2, %3, %4};"
                 :: "l"(p0), "f"(v0.x), "f"(v0.y), "f"(v0.z), "f"(v0.w) : "memory");
    if (has1) {
        float4* p1 = (float4*)&g_agg2[(long)d1 * 32] + c;
        asm volatile("red.global.add.v4.f32 [%0], {%1, %2, %3, %4};"
                     :: "l"(p1), "f"(v1.x), "f"(v1.y), "f"(v1.z), "f"(v1.w) : "memory");
    }
}

// heads: features = dinv*agg2 + b2 -> out; two tiny MLPs
__global__ void k_heads(const float* __restrict__ b2,
                        const float* __restrict__ Wt1, const float* __restrict__ bt1,
                        const float* __restrict__ Wt2, const float* __restrict__ bt2,
                        const float* __restrict__ Wa1, const float* __restrict__ ba1,
                        const float* __restrict__ Wa2, const float* __restrict__ ba2,
                        float* __restrict__ out, int n) {
    __shared__ float s_b2[32];
    __shared__ float s_Wt1[32 * 16];
    __shared__ float s_bt1[16];
    __shared__ float s_Wt2[16];
    __shared__ float s_Wa1[32 * 16];
    __shared__ float s_ba1[16];
    __shared__ float s_Wa2[16 * 6];
    __shared__ float s_ba2[6];
    __shared__ float s_bt2;
    for (int t = threadIdx.x; t < 512; t += blockDim.x) { s_Wt1[t] = Wt1[t]; s_Wa1[t] = Wa1[t]; }
    for (int t = threadIdx.x; t < 96;  t += blockDim.x) s_Wa2[t] = Wa2[t];
    if (threadIdx.x < 32) s_b2[threadIdx.x] = b2[threadIdx.x];
    if (threadIdx.x < 16) { s_bt1[threadIdx.x] = bt1[threadIdx.x];
                            s_Wt2[threadIdx.x] = Wt2[threadIdx.x];
                            s_ba1[threadIdx.x] = ba1[threadIdx.x]; }
    if (threadIdx.x < 6)  s_ba2[threadIdx.x] = ba2[threadIdx.x];
    if (threadIdx.x == 0) s_bt2 = bt2[0];
    __syncthreads();

    int i = blockIdx.x * blockDim.x + threadIdx.x;
    if (i >= n) return;

    float dinv = g_dinv[i];
    float f[32];
    const float4* ag4 = (const float4*)&g_agg2[(long)i * 32];
#pragma unroll
    for (int q = 0; q < 8; q++) {
        float4 v = ag4[q];
        f[4*q+0] = v.x * dinv + s_b2[4*q+0];
        f[4*q+1] = v.y * dinv + s_b2[4*q+1];
        f[4*q+2] = v.z * dinv + s_b2[4*q+2];
        f[4*q+3] = v.w * dinv + s_b2[4*q+3];
    }

    float4* fout = (float4*)(out + (long)7 * n + (long)i * 32);
#pragma unroll
    for (int q = 0; q < 8; q++)
        fout[q] = make_float4(f[4*q], f[4*q+1], f[4*q+2], f[4*q+3]);

    float t1[16];
#pragma unroll
    for (int j = 0; j < 16; j++) {
        float s = s_bt1[j];
#pragma unroll
        for (int k = 0; k < 32; k++) s += f[k] * s_Wt1[k * 16 + j];
        t1[j] = fmaxf(s, 0.f);
    }
    float topo = s_bt2;
#pragma unroll
    for (int j = 0; j < 16; j++) topo += t1[j] * s_Wt2[j];
    out[i] = topo;

    float a1[16];
#pragma unroll
    for (int j = 0; j < 16; j++) {
        float s = s_ba1[j];
#pragma unroll
        for (int k = 0; k < 32; k++) s += f[k] * s_Wa1[k * 16 + j];
        a1[j] = fmaxf(s, 0.f);
    }
    float attr[6];
#pragma unroll
    for (int m = 0; m < 6; m++) {
        float s = s_ba2[m];
#pragma unroll
        for (int j = 0; j < 16; j++) s += a1[j] * s_Wa2[j * 6 + m];
        attr[m] = s;
    }
    long nb = n;
    out[nb     + (long)i * 3 + 0] = attr[0];
    out[nb     + (long)i * 3 + 1] = attr[1];
    out[nb     + (long)i * 3 + 2] = attr[2];
    out[nb * 4 + (long)i * 3 + 0] = attr[3];
    out[nb * 4 + (long)i * 3 + 1] = attr[4];
    out[nb * 4 + (long)i * 3 + 2] = attr[5];
}

// ---------------------------------------------------------------------------
extern "C" void kernel_launch(void* const* d_in, const int* in_sizes, int n_in,
                              void* d_out, int out_size) {
    const float* x   = (const float*)d_in[0];
    const int*   ei  = (const int*)d_in[1];
    const float* W1  = (const float*)d_in[2];
    const float* b1  = (const float*)d_in[3];
    const float* W2  = (const float*)d_in[4];
    const float* b2  = (const float*)d_in[5];
    const float* Wt1 = (const float*)d_in[6];
    const float* bt1 = (const float*)d_in[7];
    const float* Wt2 = (const float*)d_in[8];
    const float* bt2 = (const float*)d_in[9];
    const float* Wa1 = (const float*)d_in[10];
    const float* ba1 = (const float*)d_in[11];
    const float* Wa2 = (const float*)d_in[12];
    const float* ba2 = (const float*)d_in[13];
    float* out = (float*)d_out;

    int n  = in_sizes[0] / 6;
    int ne = in_sizes[1] / 2;
    const int* src = ei;
    const int* dst = ei + ne;

    const int B = 256;
    int gn = (n + B - 1) / B;
    int ge = (ne + B - 1) / B;
    int half = (ne + 1) >> 1;
    int gs1 = (half + B - 1) / B;
    long s2 = (long)half * 8;
    int gs2 = (int)((s2 + B - 1) / B);

    k_deg_init <<<gn, B>>>(n);
    k_deg_edges<<<ge, B>>>(dst, ne);
    k_prep     <<<gn, B>>>(x, n);
    k_scat1    <<<gs1, B>>>(src, dst, ne);
    k_node     <<<gn, B>>>(W1, b1, W2, n);
    k_scat2    <<<gs2, B>>>(src, dst, ne, half);
    k_heads    <<<gn, B>>>(b2, Wt1, bt1, Wt2, bt2, Wa1, ba1, Wa2, ba2, out, n);
}